// round 12
// baseline (speedup 1.0000x reference)
#include <cuda_runtime.h>
#include <cuda_bf16.h>
#include <cuda_fp16.h>
#include <cuda_fp8.h>
#include <math.h>
#include <stdint.h>

// ----------------------------------------------------------------------------
// Problem constants
// ----------------------------------------------------------------------------
#define NS   16384
#define INF_ 1024
#define H_   2048
#define NC   10
#define PRIOR_VAR 100.0

#define SCALE_W   64.0f
#define SCALE_H   8.0f
#define INV_G1    (1.0f / SCALE_W)
#define INV_G2    (1.0f / (SCALE_W * SCALE_H))

// ----------------------------------------------------------------------------
// Scratch (static device globals — no allocations allowed)
// ----------------------------------------------------------------------------
__device__ unsigned char g_Xq [NS * INF_];          // 16 MB
__device__ unsigned char g_W1q[H_ * INF_];          //  2 MB
__device__ unsigned char g_W2q[H_ * H_];            //  4 MB
__device__ unsigned char g_h1q[(size_t)NS * H_];    // 32 MB
__device__ __nv_bfloat16 g_h2 [(size_t)NS * H_];    // 64 MB

// ----------------------------------------------------------------------------
// PTX helpers
// ----------------------------------------------------------------------------
__device__ __forceinline__ void cp16(uint32_t dst, const void* src) {
    asm volatile("cp.async.cg.shared.global [%0], [%1], 16;" :: "r"(dst), "l"(src));
}
__device__ __forceinline__ void cp_commit() {
    asm volatile("cp.async.commit_group;");
}
template<int N> __device__ __forceinline__ void cp_wait() {
    asm volatile("cp.async.wait_group %0;" :: "n"(N));
}
__device__ __forceinline__ void ldsm_x4(uint32_t* r, uint32_t addr) {
    asm volatile("ldmatrix.sync.aligned.m8n8.x4.shared.b16 {%0,%1,%2,%3}, [%4];"
                 : "=r"(r[0]), "=r"(r[1]), "=r"(r[2]), "=r"(r[3]) : "r"(addr));
}
__device__ __forceinline__ void mma_fp8_h(uint32_t* d, const uint32_t* a,
                                          const uint32_t* b) {
    asm volatile("mma.sync.aligned.m16n8k32.row.col.f16.e4m3.e4m3.f16 "
                 "{%0,%1}, {%2,%3,%4,%5}, {%6,%7}, {%0,%1};"
                 : "+r"(d[0]), "+r"(d[1])
                 : "r"(a[0]), "r"(a[1]), "r"(a[2]), "r"(a[3]),
                   "r"(b[0]), "r"(b[1]));
}
__device__ __forceinline__ unsigned char f2e4m3(float v) {
    return (unsigned char)__nv_cvt_float_to_fp8(v, __NV_SATFINITE, __NV_E4M3);
}

// ----------------------------------------------------------------------------
// FP8 GEMM (f16 accum) + bias + activation.  (R6 config — FROZEN)
//   which=0: g_h1q = fp8(8 * relu(Xq @ W1q^T / 64 + b1))        K=1024
//   which=1: g_h2  = bf16(relu(h1q @ W2q^T / 512 + b2))         K=2048
// CTA 256x128, BK=64B, 3-stage cp.async, 8 warps (4m x 2n, warp tile 64x64).
// ----------------------------------------------------------------------------
#define BM 256
#define BN 128
#define BK 64
#define STAGES 3
#define ROWB 80
#define A_STG (BM * ROWB)
#define B_STG (BN * ROWB)
#define STG_BYTES (A_STG + B_STG)
#define SMEM_DYN (STAGES * STG_BYTES)  // 92160

__global__ __launch_bounds__(256, 2)
void fp8_gemm_kernel(int which, const float* __restrict__ bias, int K)
{
    extern __shared__ unsigned char smem[];
    const unsigned char* __restrict__ A = (which == 0) ? g_Xq  : g_h1q;
    const unsigned char* __restrict__ B = (which == 0) ? g_W1q : g_W2q;

    uint32_t sb;
    asm("{ .reg .u64 t; cvta.to.shared.u64 t, %1; cvt.u32.u64 %0, t; }"
        : "=r"(sb) : "l"(smem));

    const int tid  = threadIdx.x;
    const int lane = tid & 31;
    const int warp = tid >> 5;
    const int wm   = warp >> 1;
    const int wn   = warp & 1;
    const int bm   = blockIdx.y * BM;
    const int bn   = blockIdx.x * BN;

    uint32_t acc[4][8][2];
    #pragma unroll
    for (int i = 0; i < 4; i++)
        #pragma unroll
        for (int j = 0; j < 8; j++) { acc[i][j][0] = 0u; acc[i][j][1] = 0u; }

    const int KT = K / BK;

    auto load_stage = [&](int st, int kt) {
        uint32_t aB = sb + st * STG_BYTES;
        uint32_t bB = aB + A_STG;
        const unsigned char* Ap = A + (size_t)bm * K + kt * BK;
        const unsigned char* Bp = B + (size_t)bn * K + kt * BK;
        #pragma unroll
        for (int q = 0; q < 4; q++) {
            int idx = tid + q * 256;
            int r = idx >> 2, c = (idx & 3) * 16;
            cp16(aB + r * ROWB + c, Ap + (size_t)r * K + c);
        }
        #pragma unroll
        for (int q = 0; q < 2; q++) {
            int idx = tid + q * 256;
            int r = idx >> 2, c = (idx & 3) * 16;
            cp16(bB + r * ROWB + c, Bp + (size_t)r * K + c);
        }
    };

    #pragma unroll
    for (int p = 0; p < STAGES - 1; p++) { load_stage(p, p); cp_commit(); }

    const uint32_t aOffBase =
        (uint32_t)((wm * 64 + (lane & 15)) * ROWB + (lane >> 4) * 16);
    const uint32_t bOffBase =
        (uint32_t)((wn * 64 + ((lane >> 4) & 1) * 8 + (lane & 7)) * ROWB +
                   ((lane >> 3) & 1) * 16);

    for (int i = 0; i < KT; i++) {
        const int s = i % STAGES;
        cp_wait<STAGES - 2>();
        __syncthreads();
        if (i + STAGES - 1 < KT) load_stage((i + STAGES - 1) % STAGES, i + STAGES - 1);
        cp_commit();

        const uint32_t aBase = sb + s * STG_BYTES;
        const uint32_t bBase = aBase + A_STG;
        #pragma unroll
        for (int ks = 0; ks < 2; ks++) {
            uint32_t aF[4][4];
            uint32_t bF[4][4];
            #pragma unroll
            for (int mi = 0; mi < 4; mi++)
                ldsm_x4(aF[mi], aBase + ks * 32 + aOffBase + mi * 16 * ROWB);
            #pragma unroll
            for (int njp = 0; njp < 4; njp++)
                ldsm_x4(bF[njp], bBase + ks * 32 + bOffBase + njp * 16 * ROWB);
            #pragma unroll
            for (int njp = 0; njp < 4; njp++) {
                #pragma unroll
                for (int h = 0; h < 2; h++) {
                    #pragma unroll
                    for (int mi = 0; mi < 4; mi++)
                        mma_fp8_h(acc[mi][njp * 2 + h], aF[mi], &bF[njp][2 * h]);
                }
            }
        }
    }

    // epilogue
    const float inv = (which == 0) ? INV_G1 : INV_G2;
    #pragma unroll
    for (int mi = 0; mi < 4; mi++) {
        int row0 = bm + wm * 64 + mi * 16 + (lane >> 2);
        #pragma unroll
        for (int nj = 0; nj < 8; nj++) {
            int col = bn + wn * 64 + nj * 8 + 2 * (lane & 3);
            float bv0 = __ldg(bias + col), bv1 = __ldg(bias + col + 1);
            float2 f01 = __half22float2(*(const __half2*)&acc[mi][nj][0]);
            float2 f23 = __half22float2(*(const __half2*)&acc[mi][nj][1]);
            float v0 = fmaxf(f01.x * inv + bv0, 0.f);
            float v1 = fmaxf(f01.y * inv + bv1, 0.f);
            float v2 = fmaxf(f23.x * inv + bv0, 0.f);
            float v3 = fmaxf(f23.y * inv + bv1, 0.f);
            if (which == 0) {
                unsigned short p0 = (unsigned short)f2e4m3(v0 * SCALE_H) |
                                    ((unsigned short)f2e4m3(v1 * SCALE_H) << 8);
                unsigned short p1 = (unsigned short)f2e4m3(v2 * SCALE_H) |
                                    ((unsigned short)f2e4m3(v3 * SCALE_H) << 8);
                *(unsigned short*)(g_h1q + (size_t)row0 * H_ + col)       = p0;
                *(unsigned short*)(g_h1q + (size_t)(row0 + 8) * H_ + col) = p1;
            } else {
                *(__nv_bfloat162*)(g_h2 + (size_t)row0 * H_ + col) =
                    __floats2bfloat162_rn(v0, v1);
                *(__nv_bfloat162*)(g_h2 + (size_t)(row0 + 8) * H_ + col) =
                    __floats2bfloat162_rn(v2, v3);
            }
        }
    }
}

// ----------------------------------------------------------------------------
// convX: fp32 -> fp8 for X only (no sumsq).
// ----------------------------------------------------------------------------
__global__ void convX_kernel(const float* __restrict__ in)
{
    const int gsz = gridDim.x * blockDim.x;
    const int gt  = blockIdx.x * blockDim.x + threadIdx.x;
    const int n4  = (NS * INF_) >> 2;
    for (int i = gt; i < n4; i += gsz) {
        float4 v = ((const float4*)in)[i];
        uint32_t p = (uint32_t)f2e4m3(v.x)
                   | ((uint32_t)f2e4m3(v.y) << 8)
                   | ((uint32_t)f2e4m3(v.z) << 16)
                   | ((uint32_t)f2e4m3(v.w) << 24);
        ((uint32_t*)g_Xq)[i] = p;
    }
}

// ----------------------------------------------------------------------------
// param_kernel: converts W1,W2 to fp8 AND accumulates sum-of-squares over all
// six parameter tensors (W1,b1,W2,b2,W3,b3) in ONE launch.
// ----------------------------------------------------------------------------
__global__ void param_kernel(const float* __restrict__ W1,
                             const float* __restrict__ b1, int nb1,
                             const float* __restrict__ W2,
                             const float* __restrict__ b2, int nb2,
                             const float* __restrict__ W3, int nW3,
                             const float* __restrict__ b3, int nb3,
                             float* __restrict__ out)
{
    const int gsz = gridDim.x * blockDim.x;
    const int gt  = blockIdx.x * blockDim.x + threadIdx.x;
    float s = 0.f;

    // W1: convert (x SCALE_W) + sumsq
    for (int i = gt; i < (H_ * INF_) >> 2; i += gsz) {
        float4 v = ((const float4*)W1)[i];
        uint32_t p = (uint32_t)f2e4m3(v.x * SCALE_W)
                   | ((uint32_t)f2e4m3(v.y * SCALE_W) << 8)
                   | ((uint32_t)f2e4m3(v.z * SCALE_W) << 16)
                   | ((uint32_t)f2e4m3(v.w * SCALE_W) << 24);
        ((uint32_t*)g_W1q)[i] = p;
        s += v.x * v.x + v.y * v.y + v.z * v.z + v.w * v.w;
    }
    // W2: convert (x SCALE_W) + sumsq
    for (int i = gt; i < (H_ * H_) >> 2; i += gsz) {
        float4 v = ((const float4*)W2)[i];
        uint32_t p = (uint32_t)f2e4m3(v.x * SCALE_W)
                   | ((uint32_t)f2e4m3(v.y * SCALE_W) << 8)
                   | ((uint32_t)f2e4m3(v.z * SCALE_W) << 16)
                   | ((uint32_t)f2e4m3(v.w * SCALE_W) << 24);
        ((uint32_t*)g_W2q)[i] = p;
        s += v.x * v.x + v.y * v.y + v.z * v.z + v.w * v.w;
    }
    // small tensors: sumsq only
    for (int i = gt; i < nb1; i += gsz) { float v = b1[i]; s += v * v; }
    for (int i = gt; i < nb2; i += gsz) { float v = b2[i]; s += v * v; }
    for (int i = gt; i < nW3; i += gsz) { float v = W3[i]; s += v * v; }
    for (int i = gt; i < nb3; i += gsz) { float v = b3[i]; s += v * v; }

    #pragma unroll
    for (int ofs = 16; ofs; ofs >>= 1) s += __shfl_xor_sync(0xFFFFFFFFu, s, ofs);
    __shared__ float ws[8];
    if ((threadIdx.x & 31) == 0) ws[threadIdx.x >> 5] = s;
    __syncthreads();
    if (threadIdx.x < 8) {
        float t = ws[threadIdx.x];
        #pragma unroll
        for (int ofs = 4; ofs; ofs >>= 1) t += __shfl_xor_sync(0xFFu, t, ofs);
        if (threadIdx.x == 0) atomicAdd(out, (float)(-0.5 / PRIOR_VAR) * t);
    }
}

// ----------------------------------------------------------------------------
// Fused head: logits = h2 @ W3^T + b3; sum log_softmax(logits)[Y].
// 16-byte vectorized loads (8 bf16 per lane per step).
// ----------------------------------------------------------------------------
__global__ __launch_bounds__(256)
void loss_kernel(const float* __restrict__ W3, const float* __restrict__ b3,
                 const int* __restrict__ Y, float* __restrict__ out)
{
    __shared__ __align__(16) __nv_bfloat16 sW[NC * H_];
    __shared__ float sSum;
    const int tid = threadIdx.x;
    if (tid == 0) sSum = 0.f;
    for (int i = tid; i < NC * H_ / 2; i += 256) {
        float2 w2 = ((const float2*)W3)[i];
        *(__nv_bfloat162*)(sW + 2 * i) = __floats2bfloat162_rn(w2.x, w2.y);
    }
    __syncthreads();

    const int lane = tid & 31, warp = tid >> 5;
    float local = 0.f;
    #pragma unroll
    for (int rr = 0; rr < 2; rr++) {
        int row = blockIdx.x * 16 + warp * 2 + rr;
        const __nv_bfloat16* hr = g_h2 + (size_t)row * H_;
        float acc[NC];
        #pragma unroll
        for (int c = 0; c < NC; c++) acc[c] = 0.f;
        #pragma unroll
        for (int i = 0; i < H_ / 256; i++) {       // 8 iters, 8 bf16/lane
            int k = i * 256 + lane * 8;
            uint4 hp = *(const uint4*)(hr + k);
            float2 h0 = __bfloat1622float2(*(const __nv_bfloat162*)&hp.x);
            float2 h1 = __bfloat1622float2(*(const __nv_bfloat162*)&hp.y);
            float2 h2v = __bfloat1622float2(*(const __nv_bfloat162*)&hp.z);
            float2 h3 = __bfloat1622float2(*(const __nv_bfloat162*)&hp.w);
            #pragma unroll
            for (int c = 0; c < NC; c++) {
                uint4 wp = *(const uint4*)(sW + c * H_ + k);
                float2 w0 = __bfloat1622float2(*(const __nv_bfloat162*)&wp.x);
                float2 w1 = __bfloat1622float2(*(const __nv_bfloat162*)&wp.y);
                float2 w2 = __bfloat1622float2(*(const __nv_bfloat162*)&wp.z);
                float2 w3 = __bfloat1622float2(*(const __nv_bfloat162*)&wp.w);
                acc[c] += h0.x * w0.x + h0.y * w0.y + h1.x * w1.x + h1.y * w1.y
                        + h2v.x * w2.x + h2v.y * w2.y + h3.x * w3.x + h3.y * w3.y;
            }
        }
        #pragma unroll
        for (int c = 0; c < NC; c++) {
            #pragma unroll
            for (int o = 16; o; o >>= 1)
                acc[c] += __shfl_xor_sync(0xFFFFFFFFu, acc[c], o);
        }
        if (lane == 0) {
            float lg[NC];
            float m = -1e30f;
            #pragma unroll
            for (int c = 0; c < NC; c++) {
                lg[c] = acc[c] + b3[c];
                m = fmaxf(m, lg[c]);
            }
            float se = 0.f;
            #pragma unroll
            for (int c = 0; c < NC; c++) se += expf(lg[c] - m);
            local += lg[Y[row]] - (m + logf(se));
        }
    }
    if (lane == 0) atomicAdd(&sSum, local);
    __syncthreads();
    if (tid == 0) atomicAdd(out, sSum);
}

__global__ void init_out_kernel(float* out, float c) { out[0] = c; }

// ----------------------------------------------------------------------------
// kernel_launch  (6 launches)
// ----------------------------------------------------------------------------
extern "C" void kernel_launch(void* const* d_in, const int* in_sizes, int n_in,
                              void* d_out, int out_size)
{
    const float* X  = (const float*)d_in[0];
    const int*   Y  = (const int*)  d_in[1];
    const float* W1 = (const float*)d_in[2];
    const float* b1 = (const float*)d_in[3];
    const float* W2 = (const float*)d_in[4];
    const float* b2 = (const float*)d_in[5];
    const float* W3 = (const float*)d_in[6];
    const float* b3 = (const float*)d_in[7];
    float* out = (float*)d_out;

    cudaFuncSetAttribute(fp8_gemm_kernel,
                         cudaFuncAttributeMaxDynamicSharedMemorySize, SMEM_DYN);

    double d = 0.0;
    for (int i = 2; i < 8; i++) d += (double)in_sizes[i];
    float cterm = (float)(-0.5 * d * log(2.0 * M_PI * PRIOR_VAR));
    init_out_kernel<<<1, 1>>>(out, cterm);                              // 0

    convX_kernel<<<4096, 256>>>(X);                                     // 1
    param_kernel<<<2048, 256>>>(W1, b1, in_sizes[3], W2, b2, in_sizes[5],
                                W3, in_sizes[6], b3, in_sizes[7], out); // 2

    dim3 grid(H_ / BN, NS / BM);   // (16, 64)
    fp8_gemm_kernel<<<grid, 256, SMEM_DYN>>>(0, b1, INF_);              // 3
    fp8_gemm_kernel<<<grid, 256, SMEM_DYN>>>(1, b2, H_);                // 4

    loss_kernel<<<NS / 16, 256>>>(W3, b3, Y, out);                      // 5
}

// round 13
// speedup vs baseline: 1.1742x; 1.1742x over previous
#include <cuda_runtime.h>
#include <cuda_bf16.h>
#include <cuda_fp16.h>
#include <cuda_fp8.h>
#include <math.h>
#include <stdint.h>

// ----------------------------------------------------------------------------
// Problem constants
// ----------------------------------------------------------------------------
#define NS   16384
#define INF_ 1024
#define H_   2048
#define NC   10
#define PRIOR_VAR 100.0

#define SCALE_W   64.0f
#define SCALE_H   8.0f
#define INV_G1    (1.0f / SCALE_W)
#define INV_G2    (1.0f / (SCALE_W * SCALE_H))

// ----------------------------------------------------------------------------
// Scratch (static device globals — no allocations allowed)
// ----------------------------------------------------------------------------
__device__ unsigned char g_Xq [NS * INF_];          // 16 MB
__device__ unsigned char g_W1q[H_ * INF_];          //  2 MB
__device__ unsigned char g_W2q[H_ * H_];            //  4 MB
__device__ unsigned char g_h1q[(size_t)NS * H_];    // 32 MB
__device__ __nv_bfloat16 g_h2 [(size_t)NS * H_];    // 64 MB

// ----------------------------------------------------------------------------
// PTX helpers
// ----------------------------------------------------------------------------
__device__ __forceinline__ void cp16(uint32_t dst, const void* src) {
    asm volatile("cp.async.cg.shared.global [%0], [%1], 16;" :: "r"(dst), "l"(src));
}
__device__ __forceinline__ void cp_commit() {
    asm volatile("cp.async.commit_group;");
}
template<int N> __device__ __forceinline__ void cp_wait() {
    asm volatile("cp.async.wait_group %0;" :: "n"(N));
}
__device__ __forceinline__ void ldsm_x4(uint32_t* r, uint32_t addr) {
    asm volatile("ldmatrix.sync.aligned.m8n8.x4.shared.b16 {%0,%1,%2,%3}, [%4];"
                 : "=r"(r[0]), "=r"(r[1]), "=r"(r[2]), "=r"(r[3]) : "r"(addr));
}
__device__ __forceinline__ void mma_fp8_h(uint32_t* d, const uint32_t* a,
                                          const uint32_t* b) {
    asm volatile("mma.sync.aligned.m16n8k32.row.col.f16.e4m3.e4m3.f16 "
                 "{%0,%1}, {%2,%3,%4,%5}, {%6,%7}, {%0,%1};"
                 : "+r"(d[0]), "+r"(d[1])
                 : "r"(a[0]), "r"(a[1]), "r"(a[2]), "r"(a[3]),
                   "r"(b[0]), "r"(b[1]));
}
__device__ __forceinline__ unsigned char f2e4m3(float v) {
    return (unsigned char)__nv_cvt_float_to_fp8(v, __NV_SATFINITE, __NV_E4M3);
}

// ----------------------------------------------------------------------------
// FP8 GEMM (f16 accum) + bias + activation.
//   which=0: g_h1q = fp8(8 * relu(Xq @ W1q^T / 64 + b1))        K=1024
//   which=1: g_h2  = bf16(relu(h1q @ W2q^T / 512 + b2))         K=2048
// CTA 128x128, BK=64B, 3-stage cp.async, 8 warps (4m x 2n, warp tile 32x64).
// OCCUPANCY EXPERIMENT: __launch_bounds__(256,3) -> 24 warps/SM, ~85 regs cap.
// ----------------------------------------------------------------------------
#define BM 128
#define BN 128
#define BK 64
#define STAGES 3
#define ROWB 80
#define HALF_STG (BM * ROWB)
#define STG_BYTES (2 * HALF_STG)
#define SMEM_DYN (STAGES * STG_BYTES)  // 61440; x3 CTAs = 184320 <= 227KB

__global__ __launch_bounds__(256, 3)
void fp8_gemm_kernel(int which, const float* __restrict__ bias, int K)
{
    extern __shared__ unsigned char smem[];
    const unsigned char* __restrict__ A = (which == 0) ? g_Xq  : g_h1q;
    const unsigned char* __restrict__ B = (which == 0) ? g_W1q : g_W2q;

    uint32_t sb;
    asm("{ .reg .u64 t; cvta.to.shared.u64 t, %1; cvt.u32.u64 %0, t; }"
        : "=r"(sb) : "l"(smem));

    const int tid  = threadIdx.x;
    const int lane = tid & 31;
    const int warp = tid >> 5;
    const int wm   = warp >> 1;
    const int wn   = warp & 1;
    const int bm   = blockIdx.y * BM;
    const int bn   = blockIdx.x * BN;

    uint32_t acc[2][8][2];   // 32 regs
    #pragma unroll
    for (int i = 0; i < 2; i++)
        #pragma unroll
        for (int j = 0; j < 8; j++) { acc[i][j][0] = 0u; acc[i][j][1] = 0u; }

    const int KT = K / BK;

    auto load_stage = [&](int st, int kt) {
        uint32_t aB = sb + st * STG_BYTES;
        uint32_t bB = aB + HALF_STG;
        const unsigned char* Ap = A + (size_t)bm * K + kt * BK;
        const unsigned char* Bp = B + (size_t)bn * K + kt * BK;
        #pragma unroll
        for (int q = 0; q < 2; q++) {
            int idx = tid + q * 256;
            int r = idx >> 2, c = (idx & 3) * 16;
            cp16(aB + r * ROWB + c, Ap + (size_t)r * K + c);
            cp16(bB + r * ROWB + c, Bp + (size_t)r * K + c);
        }
    };

    #pragma unroll
    for (int p = 0; p < STAGES - 1; p++) { load_stage(p, p); cp_commit(); }

    const int aRow = wm * 32 + (lane & 15);
    const int aCol = (lane >> 4) * 16;
    const uint32_t aOff0 = (uint32_t)(aRow * ROWB + aCol);
    const uint32_t aOff1 = (uint32_t)((aRow + 16) * ROWB + aCol);
    const int bRow = wn * 64 + ((lane >> 4) & 1) * 8 + (lane & 7);
    const int bCol = ((lane >> 3) & 1) * 16;
    const uint32_t bOffBase = (uint32_t)(bRow * ROWB + bCol);

    for (int i = 0; i < KT; i++) {
        const int s = i % STAGES;
        cp_wait<STAGES - 2>();
        __syncthreads();
        if (i + STAGES - 1 < KT) load_stage((i + STAGES - 1) % STAGES, i + STAGES - 1);
        cp_commit();

        const uint32_t aBase = sb + s * STG_BYTES;
        const uint32_t bBase = aBase + HALF_STG;
        #pragma unroll
        for (int ks = 0; ks < 2; ks++) {
            uint32_t aF[2][4];
            uint32_t bF[4][4];
            ldsm_x4(aF[0], aBase + ks * 32 + aOff0);
            ldsm_x4(aF[1], aBase + ks * 32 + aOff1);
            #pragma unroll
            for (int njp = 0; njp < 4; njp++)
                ldsm_x4(bF[njp], bBase + ks * 32 + bOffBase + njp * 16 * ROWB);
            #pragma unroll
            for (int njp = 0; njp < 4; njp++) {
                #pragma unroll
                for (int h = 0; h < 2; h++) {
                    mma_fp8_h(acc[0][njp * 2 + h], aF[0], &bF[njp][2 * h]);
                    mma_fp8_h(acc[1][njp * 2 + h], aF[1], &bF[njp][2 * h]);
                }
            }
        }
    }

    // epilogue
    const float inv = (which == 0) ? INV_G1 : INV_G2;
    #pragma unroll
    for (int mi = 0; mi < 2; mi++) {
        int row0 = bm + wm * 32 + mi * 16 + (lane >> 2);
        #pragma unroll
        for (int nj = 0; nj < 8; nj++) {
            int col = bn + wn * 64 + nj * 8 + 2 * (lane & 3);
            float bv0 = __ldg(bias + col), bv1 = __ldg(bias + col + 1);
            float2 f01 = __half22float2(*(const __half2*)&acc[mi][nj][0]);
            float2 f23 = __half22float2(*(const __half2*)&acc[mi][nj][1]);
            float v0 = fmaxf(f01.x * inv + bv0, 0.f);
            float v1 = fmaxf(f01.y * inv + bv1, 0.f);
            float v2 = fmaxf(f23.x * inv + bv0, 0.f);
            float v3 = fmaxf(f23.y * inv + bv1, 0.f);
            if (which == 0) {
                unsigned short p0 = (unsigned short)f2e4m3(v0 * SCALE_H) |
                                    ((unsigned short)f2e4m3(v1 * SCALE_H) << 8);
                unsigned short p1 = (unsigned short)f2e4m3(v2 * SCALE_H) |
                                    ((unsigned short)f2e4m3(v3 * SCALE_H) << 8);
                *(unsigned short*)(g_h1q + (size_t)row0 * H_ + col)       = p0;
                *(unsigned short*)(g_h1q + (size_t)(row0 + 8) * H_ + col) = p1;
            } else {
                *(__nv_bfloat162*)(g_h2 + (size_t)row0 * H_ + col) =
                    __floats2bfloat162_rn(v0, v1);
                *(__nv_bfloat162*)(g_h2 + (size_t)(row0 + 8) * H_ + col) =
                    __floats2bfloat162_rn(v2, v3);
            }
        }
    }
}

// ----------------------------------------------------------------------------
// Fused fp32 -> fp8 convert (with scale) + optional prior sum-of-squares.
// ----------------------------------------------------------------------------
__global__ void conv_sumsq_kernel(const float* __restrict__ in, int n,
                                  int dst, float scale, int do_sum,
                                  float* __restrict__ out)
{
    unsigned char* o = (dst == 0) ? g_Xq : (dst == 1) ? g_W1q : g_W2q;
    float s = 0.f;
    const int gsz = gridDim.x * blockDim.x;
    const int gt  = blockIdx.x * blockDim.x + threadIdx.x;
    const int n4  = n >> 2;
    for (int i = gt; i < n4; i += gsz) {
        float4 v = ((const float4*)in)[i];
        uint32_t p = (uint32_t)f2e4m3(v.x * scale)
                   | ((uint32_t)f2e4m3(v.y * scale) << 8)
                   | ((uint32_t)f2e4m3(v.z * scale) << 16)
                   | ((uint32_t)f2e4m3(v.w * scale) << 24);
        ((uint32_t*)o)[i] = p;
        s += v.x * v.x + v.y * v.y + v.z * v.z + v.w * v.w;
    }
    if (!do_sum) return;
    #pragma unroll
    for (int ofs = 16; ofs; ofs >>= 1) s += __shfl_xor_sync(0xFFFFFFFFu, s, ofs);
    __shared__ float ws[8];
    if ((threadIdx.x & 31) == 0) ws[threadIdx.x >> 5] = s;
    __syncthreads();
    if (threadIdx.x < 8) {
        float t = ws[threadIdx.x];
        #pragma unroll
        for (int ofs = 4; ofs; ofs >>= 1) t += __shfl_xor_sync(0xFFu, t, ofs);
        if (threadIdx.x == 0) atomicAdd(out, (float)(-0.5 / PRIOR_VAR) * t);
    }
}

// ----------------------------------------------------------------------------
// Fused sum-of-squares over 4 small parameter arrays (one launch).
// ----------------------------------------------------------------------------
__global__ void sumsq4_kernel(const float* __restrict__ p0, int n0,
                              const float* __restrict__ p1, int n1,
                              const float* __restrict__ p2, int n2,
                              const float* __restrict__ p3, int n3,
                              float* __restrict__ out)
{
    float s = 0.f;
    const int gsz = gridDim.x * blockDim.x;
    const int gt  = blockIdx.x * blockDim.x + threadIdx.x;
    for (int i = gt; i < n0; i += gsz) { float v = p0[i]; s += v * v; }
    for (int i = gt; i < n1; i += gsz) { float v = p1[i]; s += v * v; }
    for (int i = gt; i < n2; i += gsz) { float v = p2[i]; s += v * v; }
    for (int i = gt; i < n3; i += gsz) { float v = p3[i]; s += v * v; }
    #pragma unroll
    for (int ofs = 16; ofs; ofs >>= 1) s += __shfl_xor_sync(0xFFFFFFFFu, s, ofs);
    __shared__ float ws[8];
    if ((threadIdx.x & 31) == 0) ws[threadIdx.x >> 5] = s;
    __syncthreads();
    if (threadIdx.x < 8) {
        float t = ws[threadIdx.x];
        #pragma unroll
        for (int ofs = 4; ofs; ofs >>= 1) t += __shfl_xor_sync(0xFFu, t, ofs);
        if (threadIdx.x == 0) atomicAdd(out, (float)(-0.5 / PRIOR_VAR) * t);
    }
}

// ----------------------------------------------------------------------------
// Fused head: logits = h2 @ W3^T + b3; sum log_softmax(logits)[Y].
// (R11 version — 8-byte vectorized loads)
// ----------------------------------------------------------------------------
__global__ __launch_bounds__(256)
void loss_kernel(const float* __restrict__ W3, const float* __restrict__ b3,
                 const int* __restrict__ Y, float* __restrict__ out)
{
    __shared__ __nv_bfloat16 sW[NC * H_];
    __shared__ float sSum;
    const int tid = threadIdx.x;
    if (tid == 0) sSum = 0.f;
    for (int i = tid; i < NC * H_ / 2; i += 256) {
        float2 w2 = ((const float2*)W3)[i];
        *(__nv_bfloat162*)(sW + 2 * i) = __floats2bfloat162_rn(w2.x, w2.y);
    }
    __syncthreads();

    const int lane = tid & 31, warp = tid >> 5;
    float local = 0.f;
    #pragma unroll
    for (int rr = 0; rr < 2; rr++) {
        int row = blockIdx.x * 16 + warp * 2 + rr;
        const __nv_bfloat16* hr = g_h2 + (size_t)row * H_;
        float acc[NC];
        #pragma unroll
        for (int c = 0; c < NC; c++) acc[c] = 0.f;
        #pragma unroll 4
        for (int i = 0; i < H_ / 128; i++) {
            int k = i * 128 + lane * 4;
            uint2 hp = *(const uint2*)(hr + k);
            float2 ha = __bfloat1622float2(*(const __nv_bfloat162*)&hp.x);
            float2 hb = __bfloat1622float2(*(const __nv_bfloat162*)&hp.y);
            #pragma unroll
            for (int c = 0; c < NC; c++) {
                uint2 wp = *(const uint2*)(sW + c * H_ + k);
                float2 wa = __bfloat1622float2(*(const __nv_bfloat162*)&wp.x);
                float2 wb = __bfloat1622float2(*(const __nv_bfloat162*)&wp.y);
                acc[c] += ha.x * wa.x + ha.y * wa.y + hb.x * wb.x + hb.y * wb.y;
            }
        }
        #pragma unroll
        for (int c = 0; c < NC; c++) {
            #pragma unroll
            for (int o = 16; o; o >>= 1)
                acc[c] += __shfl_xor_sync(0xFFFFFFFFu, acc[c], o);
        }
        if (lane == 0) {
            float lg[NC];
            float m = -1e30f;
            #pragma unroll
            for (int c = 0; c < NC; c++) {
                lg[c] = acc[c] + b3[c];
                m = fmaxf(m, lg[c]);
            }
            float se = 0.f;
            #pragma unroll
            for (int c = 0; c < NC; c++) se += expf(lg[c] - m);
            local += lg[Y[row]] - (m + logf(se));
        }
    }
    if (lane == 0) atomicAdd(&sSum, local);
    __syncthreads();
    if (tid == 0) atomicAdd(out, sSum);
}

__global__ void init_out_kernel(float* out, float c) { out[0] = c; }

// ----------------------------------------------------------------------------
// kernel_launch  (R11 structure)
// ----------------------------------------------------------------------------
extern "C" void kernel_launch(void* const* d_in, const int* in_sizes, int n_in,
                              void* d_out, int out_size)
{
    const float* X  = (const float*)d_in[0];
    const int*   Y  = (const int*)  d_in[1];
    const float* W1 = (const float*)d_in[2];
    const float* b1 = (const float*)d_in[3];
    const float* W2 = (const float*)d_in[4];
    const float* b2 = (const float*)d_in[5];
    const float* W3 = (const float*)d_in[6];
    const float* b3 = (const float*)d_in[7];
    float* out = (float*)d_out;

    cudaFuncSetAttribute(fp8_gemm_kernel,
                         cudaFuncAttributeMaxDynamicSharedMemorySize, SMEM_DYN);

    double d = 0.0;
    for (int i = 2; i < 8; i++) d += (double)in_sizes[i];
    float cterm = (float)(-0.5 * d * log(2.0 * M_PI * PRIOR_VAR));
    init_out_kernel<<<1, 1>>>(out, cterm);                              // 0

    auto conv_grid = [](int n) {
        int g = (n / 4 + 255) / 256;
        if (g > 4096) g = 4096;
        return g;
    };
    conv_sumsq_kernel<<<conv_grid(NS * INF_), 256>>>(X,  NS * INF_, 0, 1.0f,    0, out); // 1
    conv_sumsq_kernel<<<conv_grid(H_ * INF_), 256>>>(W1, H_ * INF_, 1, SCALE_W, 1, out); // 2
    conv_sumsq_kernel<<<conv_grid(H_ * H_),   256>>>(W2, H_ * H_,   2, SCALE_W, 1, out); // 3

    dim3 grid(H_ / BN, NS / BM);   // (16, 128)
    fp8_gemm_kernel<<<grid, 256, SMEM_DYN>>>(0, b1, INF_);              // 4
    fp8_gemm_kernel<<<grid, 256, SMEM_DYN>>>(1, b2, H_);                // 5

    sumsq4_kernel<<<48, 256>>>(b1, in_sizes[3], b2, in_sizes[5],
                               W3, in_sizes[6], b3, in_sizes[7], out);  // 6
    loss_kernel<<<NS / 16, 256>>>(W3, b3, Y, out);                      // 7
}

// round 14
// speedup vs baseline: 1.2611x; 1.0741x over previous
#include <cuda_runtime.h>
#include <cuda_bf16.h>
#include <cuda_fp16.h>
#include <cuda_fp8.h>
#include <math.h>
#include <stdint.h>

// ----------------------------------------------------------------------------
// Problem constants
// ----------------------------------------------------------------------------
#define NS   16384
#define INF_ 1024
#define H_   2048
#define NC   10
#define PRIOR_VAR 100.0

#define SCALE_W   64.0f
#define SCALE_H   8.0f
#define INV_G1    (1.0f / SCALE_W)
#define INV_G2    (1.0f / (SCALE_W * SCALE_H))

#define MBLKS (NS / 256)      // 64 row blocks
#define NT1   (H_ / 128)      // 16 producer tiles per row block

// ----------------------------------------------------------------------------
// Scratch (static device globals — no allocations allowed)
// ----------------------------------------------------------------------------
__device__ unsigned char g_Xq [NS * INF_];          // 16 MB
__device__ unsigned char g_W1q[H_ * INF_];          //  2 MB
__device__ unsigned char g_W2q[H_ * H_];            //  4 MB
__device__ unsigned char g_h1q[(size_t)NS * H_];    // 32 MB
__device__ __nv_bfloat16 g_h2 [(size_t)NS * H_];    // 64 MB
__device__ int           g_cnt[MBLKS];              // producer counters

// ----------------------------------------------------------------------------
// PTX helpers
// ----------------------------------------------------------------------------
__device__ __forceinline__ void cp16(uint32_t dst, const void* src) {
    asm volatile("cp.async.cg.shared.global [%0], [%1], 16;" :: "r"(dst), "l"(src));
}
__device__ __forceinline__ void cp_commit() {
    asm volatile("cp.async.commit_group;");
}
template<int N> __device__ __forceinline__ void cp_wait() {
    asm volatile("cp.async.wait_group %0;" :: "n"(N));
}
__device__ __forceinline__ void ldsm_x4(uint32_t* r, uint32_t addr) {
    asm volatile("ldmatrix.sync.aligned.m8n8.x4.shared.b16 {%0,%1,%2,%3}, [%4];"
                 : "=r"(r[0]), "=r"(r[1]), "=r"(r[2]), "=r"(r[3]) : "r"(addr));
}
__device__ __forceinline__ void mma_fp8_h(uint32_t* d, const uint32_t* a,
                                          const uint32_t* b) {
    asm volatile("mma.sync.aligned.m16n8k32.row.col.f16.e4m3.e4m3.f16 "
                 "{%0,%1}, {%2,%3,%4,%5}, {%6,%7}, {%0,%1};"
                 : "+r"(d[0]), "+r"(d[1])
                 : "r"(a[0]), "r"(a[1]), "r"(a[2]), "r"(a[3]),
                   "r"(b[0]), "r"(b[1]));
}
__device__ __forceinline__ unsigned char f2e4m3(float v) {
    return (unsigned char)__nv_cvt_float_to_fp8(v, __NV_SATFINITE, __NV_E4M3);
}

// ----------------------------------------------------------------------------
// Fused dual-GEMM (R6 mainloop, frozen). Grid 2048, linear bid:
//   bid <  1024: GEMM1 tile (produces h1q row blocks, bumps g_cnt)
//   bid >= 1024: GEMM2 tile (spins on its row block, writes g_h2)
// CTA 256x128, BK=64B, 3-stage cp.async, 8 warps, occ 2.
// ----------------------------------------------------------------------------
#define BM 256
#define BN 128
#define BK 64
#define STAGES 3
#define ROWB 80
#define A_STG (BM * ROWB)
#define B_STG (BN * ROWB)
#define STG_BYTES (A_STG + B_STG)
#define SMEM_DYN (STAGES * STG_BYTES)  // 92160

__global__ __launch_bounds__(256, 2)
void fused_gemm_kernel(const float* __restrict__ b1g,
                       const float* __restrict__ b2g)
{
    extern __shared__ unsigned char smem[];
    const int bid   = blockIdx.x;
    const int which = (bid < 1024) ? 0 : 1;
    const int t     = which ? (bid - 1024) : bid;
    const int bnIdx = t & 15;
    const int bmIdx = t >> 4;
    const int bm    = bmIdx * BM;
    const int bn    = bnIdx * BN;
    const int K     = which ? H_ : INF_;
    const float* bias = which ? b2g : b1g;

    const unsigned char* __restrict__ A = which ? g_h1q : g_Xq;
    const unsigned char* __restrict__ B = which ? g_W2q : g_W1q;

    const int tid  = threadIdx.x;

    // Consumer: wait for all 16 producers of this row block.
    if (which) {
        if (tid == 0) {
            while (atomicAdd(&g_cnt[bmIdx], 0) < NT1) __nanosleep(64);
        }
        __syncthreads();
        __threadfence();
    }

    uint32_t sb;
    asm("{ .reg .u64 t; cvta.to.shared.u64 t, %1; cvt.u32.u64 %0, t; }"
        : "=r"(sb) : "l"(smem));

    const int lane = tid & 31;
    const int warp = tid >> 5;
    const int wm   = warp >> 1;
    const int wn   = warp & 1;

    uint32_t acc[4][8][2];
    #pragma unroll
    for (int i = 0; i < 4; i++)
        #pragma unroll
        for (int j = 0; j < 8; j++) { acc[i][j][0] = 0u; acc[i][j][1] = 0u; }

    const int KT = K / BK;

    auto load_stage = [&](int st, int kt) {
        uint32_t aB = sb + st * STG_BYTES;
        uint32_t bB = aB + A_STG;
        const unsigned char* Ap = A + (size_t)bm * K + kt * BK;
        const unsigned char* Bp = B + (size_t)bn * K + kt * BK;
        #pragma unroll
        for (int q = 0; q < 4; q++) {
            int idx = tid + q * 256;
            int r = idx >> 2, c = (idx & 3) * 16;
            cp16(aB + r * ROWB + c, Ap + (size_t)r * K + c);
        }
        #pragma unroll
        for (int q = 0; q < 2; q++) {
            int idx = tid + q * 256;
            int r = idx >> 2, c = (idx & 3) * 16;
            cp16(bB + r * ROWB + c, Bp + (size_t)r * K + c);
        }
    };

    #pragma unroll
    for (int p = 0; p < STAGES - 1; p++) { load_stage(p, p); cp_commit(); }

    const uint32_t aOffBase =
        (uint32_t)((wm * 64 + (lane & 15)) * ROWB + (lane >> 4) * 16);
    const uint32_t bOffBase =
        (uint32_t)((wn * 64 + ((lane >> 4) & 1) * 8 + (lane & 7)) * ROWB +
                   ((lane >> 3) & 1) * 16);

    for (int i = 0; i < KT; i++) {
        const int s = i % STAGES;
        cp_wait<STAGES - 2>();
        __syncthreads();
        if (i + STAGES - 1 < KT) load_stage((i + STAGES - 1) % STAGES, i + STAGES - 1);
        cp_commit();

        const uint32_t aBase = sb + s * STG_BYTES;
        const uint32_t bBase = aBase + A_STG;
        #pragma unroll
        for (int ks = 0; ks < 2; ks++) {
            uint32_t aF[4][4];
            uint32_t bF[4][4];
            #pragma unroll
            for (int mi = 0; mi < 4; mi++)
                ldsm_x4(aF[mi], aBase + ks * 32 + aOffBase + mi * 16 * ROWB);
            #pragma unroll
            for (int njp = 0; njp < 4; njp++)
                ldsm_x4(bF[njp], bBase + ks * 32 + bOffBase + njp * 16 * ROWB);
            #pragma unroll
            for (int njp = 0; njp < 4; njp++) {
                #pragma unroll
                for (int h = 0; h < 2; h++) {
                    #pragma unroll
                    for (int mi = 0; mi < 4; mi++)
                        mma_fp8_h(acc[mi][njp * 2 + h], aF[mi], &bF[njp][2 * h]);
                }
            }
        }
    }

    // epilogue
    const float inv = which ? INV_G2 : INV_G1;
    #pragma unroll
    for (int mi = 0; mi < 4; mi++) {
        int row0 = bm + wm * 64 + mi * 16 + (lane >> 2);
        #pragma unroll
        for (int nj = 0; nj < 8; nj++) {
            int col = bn + wn * 64 + nj * 8 + 2 * (lane & 3);
            float bv0 = __ldg(bias + col), bv1 = __ldg(bias + col + 1);
            float2 f01 = __half22float2(*(const __half2*)&acc[mi][nj][0]);
            float2 f23 = __half22float2(*(const __half2*)&acc[mi][nj][1]);
            float v0 = fmaxf(f01.x * inv + bv0, 0.f);
            float v1 = fmaxf(f01.y * inv + bv1, 0.f);
            float v2 = fmaxf(f23.x * inv + bv0, 0.f);
            float v3 = fmaxf(f23.y * inv + bv1, 0.f);
            if (which == 0) {
                unsigned short p0 = (unsigned short)f2e4m3(v0 * SCALE_H) |
                                    ((unsigned short)f2e4m3(v1 * SCALE_H) << 8);
                unsigned short p1 = (unsigned short)f2e4m3(v2 * SCALE_H) |
                                    ((unsigned short)f2e4m3(v3 * SCALE_H) << 8);
                *(unsigned short*)(g_h1q + (size_t)row0 * H_ + col)       = p0;
                *(unsigned short*)(g_h1q + (size_t)(row0 + 8) * H_ + col) = p1;
            } else {
                *(__nv_bfloat162*)(g_h2 + (size_t)row0 * H_ + col) =
                    __floats2bfloat162_rn(v0, v1);
                *(__nv_bfloat162*)(g_h2 + (size_t)(row0 + 8) * H_ + col) =
                    __floats2bfloat162_rn(v2, v3);
            }
        }
    }

    // Producer: publish this tile.
    if (which == 0) {
        __syncthreads();
        if (tid == 0) {
            __threadfence();
            atomicAdd(&g_cnt[bmIdx], 1);
        }
    }
}

// ----------------------------------------------------------------------------
// Fused fp32 -> fp8 convert (with scale) + optional prior sum-of-squares.
// ----------------------------------------------------------------------------
__global__ void conv_sumsq_kernel(const float* __restrict__ in, int n,
                                  int dst, float scale, int do_sum,
                                  float* __restrict__ out)
{
    unsigned char* o = (dst == 0) ? g_Xq : (dst == 1) ? g_W1q : g_W2q;
    float s = 0.f;
    const int gsz = gridDim.x * blockDim.x;
    const int gt  = blockIdx.x * blockDim.x + threadIdx.x;
    const int n4  = n >> 2;
    for (int i = gt; i < n4; i += gsz) {
        float4 v = ((const float4*)in)[i];
        uint32_t p = (uint32_t)f2e4m3(v.x * scale)
                   | ((uint32_t)f2e4m3(v.y * scale) << 8)
                   | ((uint32_t)f2e4m3(v.z * scale) << 16)
                   | ((uint32_t)f2e4m3(v.w * scale) << 24);
        ((uint32_t*)o)[i] = p;
        s += v.x * v.x + v.y * v.y + v.z * v.z + v.w * v.w;
    }
    if (!do_sum) return;
    #pragma unroll
    for (int ofs = 16; ofs; ofs >>= 1) s += __shfl_xor_sync(0xFFFFFFFFu, s, ofs);
    __shared__ float ws[8];
    if ((threadIdx.x & 31) == 0) ws[threadIdx.x >> 5] = s;
    __syncthreads();
    if (threadIdx.x < 8) {
        float t = ws[threadIdx.x];
        #pragma unroll
        for (int ofs = 4; ofs; ofs >>= 1) t += __shfl_xor_sync(0xFFu, t, ofs);
        if (threadIdx.x == 0) atomicAdd(out, (float)(-0.5 / PRIOR_VAR) * t);
    }
}

// ----------------------------------------------------------------------------
// Fused sum-of-squares over 4 small parameter arrays (one launch).
// ----------------------------------------------------------------------------
__global__ void sumsq4_kernel(const float* __restrict__ p0, int n0,
                              const float* __restrict__ p1, int n1,
                              const float* __restrict__ p2, int n2,
                              const float* __restrict__ p3, int n3,
                              float* __restrict__ out)
{
    float s = 0.f;
    const int gsz = gridDim.x * blockDim.x;
    const int gt  = blockIdx.x * blockDim.x + threadIdx.x;
    for (int i = gt; i < n0; i += gsz) { float v = p0[i]; s += v * v; }
    for (int i = gt; i < n1; i += gsz) { float v = p1[i]; s += v * v; }
    for (int i = gt; i < n2; i += gsz) { float v = p2[i]; s += v * v; }
    for (int i = gt; i < n3; i += gsz) { float v = p3[i]; s += v * v; }
    #pragma unroll
    for (int ofs = 16; ofs; ofs >>= 1) s += __shfl_xor_sync(0xFFFFFFFFu, s, ofs);
    __shared__ float ws[8];
    if ((threadIdx.x & 31) == 0) ws[threadIdx.x >> 5] = s;
    __syncthreads();
    if (threadIdx.x < 8) {
        float t = ws[threadIdx.x];
        #pragma unroll
        for (int ofs = 4; ofs; ofs >>= 1) t += __shfl_xor_sync(0xFFu, t, ofs);
        if (threadIdx.x == 0) atomicAdd(out, (float)(-0.5 / PRIOR_VAR) * t);
    }
}

// ----------------------------------------------------------------------------
// Fused head: logits = h2 @ W3^T + b3; sum log_softmax(logits)[Y].
// ----------------------------------------------------------------------------
__global__ __launch_bounds__(256)
void loss_kernel(const float* __restrict__ W3, const float* __restrict__ b3,
                 const int* __restrict__ Y, float* __restrict__ out)
{
    __shared__ __nv_bfloat16 sW[NC * H_];
    __shared__ float sSum;
    const int tid = threadIdx.x;
    if (tid == 0) sSum = 0.f;
    for (int i = tid; i < NC * H_ / 2; i += 256) {
        float2 w2 = ((const float2*)W3)[i];
        *(__nv_bfloat162*)(sW + 2 * i) = __floats2bfloat162_rn(w2.x, w2.y);
    }
    __syncthreads();

    const int lane = tid & 31, warp = tid >> 5;
    float local = 0.f;
    #pragma unroll
    for (int rr = 0; rr < 2; rr++) {
        int row = blockIdx.x * 16 + warp * 2 + rr;
        const __nv_bfloat16* hr = g_h2 + (size_t)row * H_;
        float acc[NC];
        #pragma unroll
        for (int c = 0; c < NC; c++) acc[c] = 0.f;
        #pragma unroll 4
        for (int i = 0; i < H_ / 128; i++) {
            int k = i * 128 + lane * 4;
            uint2 hp = *(const uint2*)(hr + k);
            float2 ha = __bfloat1622float2(*(const __nv_bfloat162*)&hp.x);
            float2 hb = __bfloat1622float2(*(const __nv_bfloat162*)&hp.y);
            #pragma unroll
            for (int c = 0; c < NC; c++) {
                uint2 wp = *(const uint2*)(sW + c * H_ + k);
                float2 wa = __bfloat1622float2(*(const __nv_bfloat162*)&wp.x);
                float2 wb = __bfloat1622float2(*(const __nv_bfloat162*)&wp.y);
                acc[c] += ha.x * wa.x + ha.y * wa.y + hb.x * wb.x + hb.y * wb.y;
            }
        }
        #pragma unroll
        for (int c = 0; c < NC; c++) {
            #pragma unroll
            for (int o = 16; o; o >>= 1)
                acc[c] += __shfl_xor_sync(0xFFFFFFFFu, acc[c], o);
        }
        if (lane == 0) {
            float lg[NC];
            float m = -1e30f;
            #pragma unroll
            for (int c = 0; c < NC; c++) {
                lg[c] = acc[c] + b3[c];
                m = fmaxf(m, lg[c]);
            }
            float se = 0.f;
            #pragma unroll
            for (int c = 0; c < NC; c++) se += expf(lg[c] - m);
            local += lg[Y[row]] - (m + logf(se));
        }
    }
    if (lane == 0) atomicAdd(&sSum, local);
    __syncthreads();
    if (tid == 0) atomicAdd(out, sSum);
}

// init: prior constant + zero row-block counters (every graph replay).
__global__ void init_kernel(float* out, float c) {
    if (threadIdx.x == 0) out[0] = c;
    if (threadIdx.x < MBLKS) g_cnt[threadIdx.x] = 0;
}

// ----------------------------------------------------------------------------
// kernel_launch
// ----------------------------------------------------------------------------
extern "C" void kernel_launch(void* const* d_in, const int* in_sizes, int n_in,
                              void* d_out, int out_size)
{
    const float* X  = (const float*)d_in[0];
    const int*   Y  = (const int*)  d_in[1];
    const float* W1 = (const float*)d_in[2];
    const float* b1 = (const float*)d_in[3];
    const float* W2 = (const float*)d_in[4];
    const float* b2 = (const float*)d_in[5];
    const float* W3 = (const float*)d_in[6];
    const float* b3 = (const float*)d_in[7];
    float* out = (float*)d_out;

    cudaFuncSetAttribute(fused_gemm_kernel,
                         cudaFuncAttributeMaxDynamicSharedMemorySize, SMEM_DYN);

    double d = 0.0;
    for (int i = 2; i < 8; i++) d += (double)in_sizes[i];
    float cterm = (float)(-0.5 * d * log(2.0 * M_PI * PRIOR_VAR));
    init_kernel<<<1, 64>>>(out, cterm);                                 // 0

    auto conv_grid = [](int n) {
        int g = (n / 4 + 255) / 256;
        if (g > 4096) g = 4096;
        return g;
    };
    conv_sumsq_kernel<<<conv_grid(NS * INF_), 256>>>(X,  NS * INF_, 0, 1.0f,    0, out); // 1
    conv_sumsq_kernel<<<conv_grid(H_ * INF_), 256>>>(W1, H_ * INF_, 1, SCALE_W, 1, out); // 2
    conv_sumsq_kernel<<<conv_grid(H_ * H_),   256>>>(W2, H_ * H_,   2, SCALE_W, 1, out); // 3

    fused_gemm_kernel<<<2048, 256, SMEM_DYN>>>(b1, b2);                 // 4

    sumsq4_kernel<<<48, 256>>>(b1, in_sizes[3], b2, in_sizes[5],
                               W3, in_sizes[6], b3, in_sizes[7], out);  // 5
    loss_kernel<<<NS / 16, 256>>>(W3, b3, Y, out);                      // 6
}

// round 15
// speedup vs baseline: 1.3007x; 1.0313x over previous
#include <cuda_runtime.h>
#include <cuda_bf16.h>
#include <cuda_fp16.h>
#include <cuda_fp8.h>
#include <math.h>
#include <stdint.h>

// ----------------------------------------------------------------------------
// Problem constants
// ----------------------------------------------------------------------------
#define NS   16384
#define INF_ 1024
#define H_   2048
#define NC   10
#define PRIOR_VAR 100.0

#define SCALE_W   64.0f
#define SCALE_H   8.0f
#define INV_G1    (1.0f / SCALE_W)
#define INV_G2    (1.0f / (SCALE_W * SCALE_H))

#define MBLKS (NS / 256)      // 64 row blocks (GEMM BM=256)
#define NT1   (H_ / 128)      // 16 tiles per row block (BN=128)

// grid layout
#define N_CONVX  256          // 64 blocks x 4 CTAs
#define N_CONVW1 32           // 16 blocks x 2 CTAs
#define N_CONVW2 64           // 16 blocks x 4 CTAs
#define BID_SMALL (N_CONVX + N_CONVW1 + N_CONVW2)        // 352
#define BID_G1    (BID_SMALL + 1)                        // 353
#define BID_G2    (BID_G1 + 1024)                        // 1377
#define BID_LOSS  (BID_G2 + 1024)                        // 2401
#define GRID_TOT  (BID_LOSS + 1024)                      // 3425

// ----------------------------------------------------------------------------
// Scratch (static device globals — no allocations allowed)
// ----------------------------------------------------------------------------
__device__ unsigned char g_Xq [NS * INF_];          // 16 MB
__device__ unsigned char g_W1q[H_ * INF_];          //  2 MB
__device__ unsigned char g_W2q[H_ * H_];            //  4 MB
__device__ unsigned char g_h1q[(size_t)NS * H_];    // 32 MB
__device__ __nv_bfloat16 g_h2 [(size_t)NS * H_];    // 64 MB
__device__ int g_cntX [MBLKS];
__device__ int g_cntW1[NT1];
__device__ int g_cntW2[NT1];
__device__ int g_cnt1 [MBLKS];
__device__ int g_cnt2 [MBLKS];

// ----------------------------------------------------------------------------
// PTX helpers
// ----------------------------------------------------------------------------
__device__ __forceinline__ void cp16(uint32_t dst, const void* src) {
    asm volatile("cp.async.cg.shared.global [%0], [%1], 16;" :: "r"(dst), "l"(src));
}
__device__ __forceinline__ void cp_commit() {
    asm volatile("cp.async.commit_group;");
}
template<int N> __device__ __forceinline__ void cp_wait() {
    asm volatile("cp.async.wait_group %0;" :: "n"(N));
}
__device__ __forceinline__ void ldsm_x4(uint32_t* r, uint32_t addr) {
    asm volatile("ldmatrix.sync.aligned.m8n8.x4.shared.b16 {%0,%1,%2,%3}, [%4];"
                 : "=r"(r[0]), "=r"(r[1]), "=r"(r[2]), "=r"(r[3]) : "r"(addr));
}
__device__ __forceinline__ void mma_fp8_h(uint32_t* d, const uint32_t* a,
                                          const uint32_t* b) {
    asm volatile("mma.sync.aligned.m16n8k32.row.col.f16.e4m3.e4m3.f16 "
                 "{%0,%1}, {%2,%3,%4,%5}, {%6,%7}, {%0,%1};"
                 : "+r"(d[0]), "+r"(d[1])
                 : "r"(a[0]), "r"(a[1]), "r"(a[2]), "r"(a[3]),
                   "r"(b[0]), "r"(b[1]));
}
__device__ __forceinline__ unsigned char f2e4m3(float v) {
    return (unsigned char)__nv_cvt_float_to_fp8(v, __NV_SATFINITE, __NV_E4M3);
}
__device__ __forceinline__ uint32_t pack4(float4 v, float s) {
    return (uint32_t)f2e4m3(v.x * s)
         | ((uint32_t)f2e4m3(v.y * s) << 8)
         | ((uint32_t)f2e4m3(v.z * s) << 16)
         | ((uint32_t)f2e4m3(v.w * s) << 24);
}

// spin until *cnt >= target (thread 0), then block-wide fence
__device__ __forceinline__ void wait_cnt(int* cnt, int target) {
    if (threadIdx.x == 0)
        while (atomicAdd(cnt, 0) < target) __nanosleep(64);
    __syncthreads();
    __threadfence();
}
// make this CTA's writes visible, then bump counter
__device__ __forceinline__ void publish(int* cnt) {
    __threadfence();
    __syncthreads();
    if (threadIdx.x == 0) atomicAdd(cnt, 1);
}
// block-reduce s and add -0.5*s/VAR to out
__device__ __forceinline__ void prior_add(float s, float* out) {
    #pragma unroll
    for (int o = 16; o; o >>= 1) s += __shfl_xor_sync(0xFFFFFFFFu, s, o);
    __shared__ float ws[8];
    if ((threadIdx.x & 31) == 0) ws[threadIdx.x >> 5] = s;
    __syncthreads();
    if (threadIdx.x < 8) {
        float t = ws[threadIdx.x];
        #pragma unroll
        for (int o = 4; o; o >>= 1) t += __shfl_xor_sync(0xFFu, t, o);
        if (threadIdx.x == 0) atomicAdd(out, (float)(-0.5 / PRIOR_VAR) * t);
    }
}

// ----------------------------------------------------------------------------
// Mega-kernel: conv + dual GEMM + loss, ordered by bid (all deps point down).
// ----------------------------------------------------------------------------
#define BM 256
#define BN 128
#define BK 64
#define STAGES 3
#define ROWB 80
#define A_STG (BM * ROWB)
#define B_STG (BN * ROWB)
#define STG_BYTES (A_STG + B_STG)
#define SMEM_DYN (STAGES * STG_BYTES)  // 92160

__global__ __launch_bounds__(256, 2)
void mega_kernel(const float* __restrict__ X,
                 const float* __restrict__ W1, const float* __restrict__ b1,
                 const float* __restrict__ W2, const float* __restrict__ b2,
                 const float* __restrict__ W3, const float* __restrict__ b3,
                 const int*   __restrict__ Y,  float* __restrict__ out)
{
    extern __shared__ unsigned char smem[];
    const int bid = blockIdx.x;
    const int tid = threadIdx.x;

    // ---------------- conversion phase (bids 0..352) ----------------
    if (bid < N_CONVX) {
        int blk = bid >> 2, q = bid & 3;
        size_t base4 = (((size_t)blk * 256 + q * 64) * INF_) >> 2;
        const float4* src = (const float4*)X + base4;
        uint32_t* dst = (uint32_t*)g_Xq + base4;
        for (int i = tid; i < 16384; i += 256)
            dst[i] = pack4(src[i], 1.0f);
        publish(&g_cntX[blk]);
        return;
    }
    if (bid < N_CONVX + N_CONVW1) {
        int b2i = bid - N_CONVX, blk = b2i >> 1, hf = b2i & 1;
        size_t base4 = (((size_t)blk * 128 + hf * 64) * INF_) >> 2;
        const float4* src = (const float4*)W1 + base4;
        uint32_t* dst = (uint32_t*)g_W1q + base4;
        float s = 0.f;
        for (int i = tid; i < 16384; i += 256) {
            float4 v = src[i];
            dst[i] = pack4(v, SCALE_W);
            s += v.x * v.x + v.y * v.y + v.z * v.z + v.w * v.w;
        }
        prior_add(s, out);
        publish(&g_cntW1[blk]);
        return;
    }
    if (bid < BID_SMALL) {
        int b2i = bid - (N_CONVX + N_CONVW1), blk = b2i >> 2, q = b2i & 3;
        size_t base4 = (((size_t)blk * 128 + q * 32) * H_) >> 2;
        const float4* src = (const float4*)W2 + base4;
        uint32_t* dst = (uint32_t*)g_W2q + base4;
        float s = 0.f;
        for (int i = tid; i < 16384; i += 256) {
            float4 v = src[i];
            dst[i] = pack4(v, SCALE_W);
            s += v.x * v.x + v.y * v.y + v.z * v.z + v.w * v.w;
        }
        prior_add(s, out);
        publish(&g_cntW2[blk]);
        return;
    }
    if (bid == BID_SMALL) {
        float s = 0.f;
        for (int i = tid; i < H_; i += 256) { float v = b1[i]; s += v * v; }
        for (int i = tid; i < H_; i += 256) { float v = b2[i]; s += v * v; }
        for (int i = tid; i < NC * H_; i += 256) { float v = W3[i]; s += v * v; }
        for (int i = tid; i < NC; i += 256) { float v = b3[i]; s += v * v; }
        prior_add(s, out);
        return;
    }

    // ---------------- loss phase (bids >= BID_LOSS) ----------------
    if (bid >= BID_LOSS) {
        int lb = bid - BID_LOSS;                 // 0..1023, 16 rows each
        __nv_bfloat16* sW = (__nv_bfloat16*)smem;  // 40 KB of dynamic smem
        __shared__ float sSum;
        if (tid == 0) sSum = 0.f;
        for (int i = tid; i < NC * H_ / 2; i += 256) {
            float2 w2 = ((const float2*)W3)[i];
            *(__nv_bfloat162*)(sW + 2 * i) = __floats2bfloat162_rn(w2.x, w2.y);
        }
        wait_cnt(&g_cnt2[lb >> 4], NT1);         // includes __syncthreads
        const int lane = tid & 31, warp = tid >> 5;
        float local = 0.f;
        #pragma unroll
        for (int rr = 0; rr < 2; rr++) {
            int row = lb * 16 + warp * 2 + rr;
            const __nv_bfloat16* hr = g_h2 + (size_t)row * H_;
            float acc[NC];
            #pragma unroll
            for (int c = 0; c < NC; c++) acc[c] = 0.f;
            #pragma unroll 4
            for (int i = 0; i < H_ / 128; i++) {
                int k = i * 128 + lane * 4;
                uint2 hp = *(const uint2*)(hr + k);
                float2 ha = __bfloat1622float2(*(const __nv_bfloat162*)&hp.x);
                float2 hb = __bfloat1622float2(*(const __nv_bfloat162*)&hp.y);
                #pragma unroll
                for (int c = 0; c < NC; c++) {
                    uint2 wp = *(const uint2*)(sW + c * H_ + k);
                    float2 wa = __bfloat1622float2(*(const __nv_bfloat162*)&wp.x);
                    float2 wb = __bfloat1622float2(*(const __nv_bfloat162*)&wp.y);
                    acc[c] += ha.x * wa.x + ha.y * wa.y + hb.x * wb.x + hb.y * wb.y;
                }
            }
            #pragma unroll
            for (int c = 0; c < NC; c++) {
                #pragma unroll
                for (int o = 16; o; o >>= 1)
                    acc[c] += __shfl_xor_sync(0xFFFFFFFFu, acc[c], o);
            }
            if (lane == 0) {
                float lg[NC];
                float m = -1e30f;
                #pragma unroll
                for (int c = 0; c < NC; c++) {
                    lg[c] = acc[c] + b3[c];
                    m = fmaxf(m, lg[c]);
                }
                float se = 0.f;
                #pragma unroll
                for (int c = 0; c < NC; c++) se += expf(lg[c] - m);
                local += lg[Y[row]] - (m + logf(se));
            }
        }
        if (lane == 0) atomicAdd(&sSum, local);
        __syncthreads();
        if (tid == 0) atomicAdd(out, sSum);
        return;
    }

    // ---------------- GEMM phase (R14 code, frozen) ----------------
    const int which = (bid < BID_G2) ? 0 : 1;
    const int t     = which ? (bid - BID_G2) : (bid - BID_G1);
    const int bnIdx = t & 15;
    const int bmIdx = t >> 4;
    const int bm    = bmIdx * BM;
    const int bn    = bnIdx * BN;
    const int K     = which ? H_ : INF_;
    const float* bias = which ? b2 : b1;
    const unsigned char* __restrict__ A = which ? g_h1q : g_Xq;
    const unsigned char* __restrict__ B = which ? g_W2q : g_W1q;

    if (which) {
        if (tid == 0) {
            while (atomicAdd(&g_cnt1[bmIdx], 0) < NT1) __nanosleep(64);
            while (atomicAdd(&g_cntW2[bnIdx], 0) < 4)  __nanosleep(64);
        }
        __syncthreads();
        __threadfence();
    } else {
        if (tid == 0) {
            while (atomicAdd(&g_cntX[bmIdx], 0) < 4)  __nanosleep(64);
            while (atomicAdd(&g_cntW1[bnIdx], 0) < 2) __nanosleep(64);
        }
        __syncthreads();
        __threadfence();
    }

    uint32_t sb;
    asm("{ .reg .u64 t; cvta.to.shared.u64 t, %1; cvt.u32.u64 %0, t; }"
        : "=r"(sb) : "l"(smem));

    const int lane = tid & 31;
    const int warp = tid >> 5;
    const int wm   = warp >> 1;
    const int wn   = warp & 1;

    uint32_t acc[4][8][2];
    #pragma unroll
    for (int i = 0; i < 4; i++)
        #pragma unroll
        for (int j = 0; j < 8; j++) { acc[i][j][0] = 0u; acc[i][j][1] = 0u; }

    const int KT = K / BK;

    auto load_stage = [&](int st, int kt) {
        uint32_t aB = sb + st * STG_BYTES;
        uint32_t bB = aB + A_STG;
        const unsigned char* Ap = A + (size_t)bm * K + kt * BK;
        const unsigned char* Bp = B + (size_t)bn * K + kt * BK;
        #pragma unroll
        for (int q = 0; q < 4; q++) {
            int idx = tid + q * 256;
            int r = idx >> 2, c = (idx & 3) * 16;
            cp16(aB + r * ROWB + c, Ap + (size_t)r * K + c);
        }
        #pragma unroll
        for (int q = 0; q < 2; q++) {
            int idx = tid + q * 256;
            int r = idx >> 2, c = (idx & 3) * 16;
            cp16(bB + r * ROWB + c, Bp + (size_t)r * K + c);
        }
    };

    #pragma unroll
    for (int p = 0; p < STAGES - 1; p++) { load_stage(p, p); cp_commit(); }

    const uint32_t aOffBase =
        (uint32_t)((wm * 64 + (lane & 15)) * ROWB + (lane >> 4) * 16);
    const uint32_t bOffBase =
        (uint32_t)((wn * 64 + ((lane >> 4) & 1) * 8 + (lane & 7)) * ROWB +
                   ((lane >> 3) & 1) * 16);

    for (int i = 0; i < KT; i++) {
        const int s = i % STAGES;
        cp_wait<STAGES - 2>();
        __syncthreads();
        if (i + STAGES - 1 < KT) load_stage((i + STAGES - 1) % STAGES, i + STAGES - 1);
        cp_commit();

        const uint32_t aBase = sb + s * STG_BYTES;
        const uint32_t bBase = aBase + A_STG;
        #pragma unroll
        for (int ks = 0; ks < 2; ks++) {
            uint32_t aF[4][4];
            uint32_t bF[4][4];
            #pragma unroll
            for (int mi = 0; mi < 4; mi++)
                ldsm_x4(aF[mi], aBase + ks * 32 + aOffBase + mi * 16 * ROWB);
            #pragma unroll
            for (int njp = 0; njp < 4; njp++)
                ldsm_x4(bF[njp], bBase + ks * 32 + bOffBase + njp * 16 * ROWB);
            #pragma unroll
            for (int njp = 0; njp < 4; njp++) {
                #pragma unroll
                for (int h = 0; h < 2; h++) {
                    #pragma unroll
                    for (int mi = 0; mi < 4; mi++)
                        mma_fp8_h(acc[mi][njp * 2 + h], aF[mi], &bF[njp][2 * h]);
                }
            }
        }
    }

    // epilogue
    const float inv = which ? INV_G2 : INV_G1;
    #pragma unroll
    for (int mi = 0; mi < 4; mi++) {
        int row0 = bm + wm * 64 + mi * 16 + (lane >> 2);
        #pragma unroll
        for (int nj = 0; nj < 8; nj++) {
            int col = bn + wn * 64 + nj * 8 + 2 * (lane & 3);
            float bv0 = __ldg(bias + col), bv1 = __ldg(bias + col + 1);
            float2 f01 = __half22float2(*(const __half2*)&acc[mi][nj][0]);
            float2 f23 = __half22float2(*(const __half2*)&acc[mi][nj][1]);
            float v0 = fmaxf(f01.x * inv + bv0, 0.f);
            float v1 = fmaxf(f01.y * inv + bv1, 0.f);
            float v2 = fmaxf(f23.x * inv + bv0, 0.f);
            float v3 = fmaxf(f23.y * inv + bv1, 0.f);
            if (which == 0) {
                unsigned short p0 = (unsigned short)f2e4m3(v0 * SCALE_H) |
                                    ((unsigned short)f2e4m3(v1 * SCALE_H) << 8);
                unsigned short p1 = (unsigned short)f2e4m3(v2 * SCALE_H) |
                                    ((unsigned short)f2e4m3(v3 * SCALE_H) << 8);
                *(unsigned short*)(g_h1q + (size_t)row0 * H_ + col)       = p0;
                *(unsigned short*)(g_h1q + (size_t)(row0 + 8) * H_ + col) = p1;
            } else {
                *(__nv_bfloat162*)(g_h2 + (size_t)row0 * H_ + col) =
                    __floats2bfloat162_rn(v0, v1);
                *(__nv_bfloat162*)(g_h2 + (size_t)(row0 + 8) * H_ + col) =
                    __floats2bfloat162_rn(v2, v3);
            }
        }
    }

    publish(which ? &g_cnt2[bmIdx] : &g_cnt1[bmIdx]);
}

// ----------------------------------------------------------------------------
// init: prior constant + zero ALL counters (every graph replay).
// ----------------------------------------------------------------------------
__global__ void init_kernel(float* out, float c) {
    int t = threadIdx.x;
    if (t == 0) out[0] = c;
    if (t < MBLKS) { g_cntX[t] = 0; g_cnt1[t] = 0; g_cnt2[t] = 0; }
    if (t < NT1)   { g_cntW1[t] = 0; g_cntW2[t] = 0; }
}

// ----------------------------------------------------------------------------
// kernel_launch  (2 launches)
// ----------------------------------------------------------------------------
extern "C" void kernel_launch(void* const* d_in, const int* in_sizes, int n_in,
                              void* d_out, int out_size)
{
    const float* X  = (const float*)d_in[0];
    const int*   Y  = (const int*)  d_in[1];
    const float* W1 = (const float*)d_in[2];
    const float* b1 = (const float*)d_in[3];
    const float* W2 = (const float*)d_in[4];
    const float* b2 = (const float*)d_in[5];
    const float* W3 = (const float*)d_in[6];
    const float* b3 = (const float*)d_in[7];
    float* out = (float*)d_out;

    cudaFuncSetAttribute(mega_kernel,
                         cudaFuncAttributeMaxDynamicSharedMemorySize, SMEM_DYN);

    double d = 0.0;
    for (int i = 2; i < 8; i++) d += (double)in_sizes[i];
    float cterm = (float)(-0.5 * d * log(2.0 * M_PI * PRIOR_VAR));
    init_kernel<<<1, 64>>>(out, cterm);                                 // 0

    mega_kernel<<<GRID_TOT, 256, SMEM_DYN>>>(X, W1, b1, W2, b2,
                                             W3, b3, Y, out);           // 1
}

// round 16
// speedup vs baseline: 1.3288x; 1.0216x over previous
#include <cuda_runtime.h>
#include <cuda_bf16.h>
#include <cuda_fp16.h>
#include <cuda_fp8.h>
#include <math.h>
#include <stdint.h>

// ----------------------------------------------------------------------------
// Problem constants
// ----------------------------------------------------------------------------
#define NS   16384
#define INF_ 1024
#define H_   2048
#define NC   10
#define PRIOR_VAR 100.0

#define SCALE_W   64.0f
#define SCALE_H   8.0f
#define INV_G1    (1.0f / SCALE_W)
#define INV_G2    (1.0f / (SCALE_W * SCALE_H))

#define MBLKS (NS / 256)      // 64 row blocks (GEMM BM=256)
#define NT1   (H_ / 128)      // 16 tiles per row block (BN=128)

// grid layout
#define N_CONVX  256          // 64 blocks x 4 CTAs
#define N_CONVW1 32           // 16 blocks x 2 CTAs
#define N_CONVW2 64           // 16 blocks x 4 CTAs
#define BID_SMALL (N_CONVX + N_CONVW1 + N_CONVW2)        // 352
#define BID_G1    (BID_SMALL + 1)                        // 353
#define BID_G2    (BID_G1 + 1024)                        // 1377
#define BID_LOSS  (BID_G2 + 1024)                        // 2401
#define GRID_TOT  (BID_LOSS + 1024)                      // 3425

// ----------------------------------------------------------------------------
// Scratch (static device globals — no allocations allowed)
// ----------------------------------------------------------------------------
__device__ unsigned char g_Xq [NS * INF_];          // 16 MB
__device__ unsigned char g_W1q[H_ * INF_];          //  2 MB
__device__ unsigned char g_W2q[H_ * H_];            //  4 MB
__device__ unsigned char g_h1q[(size_t)NS * H_];    // 32 MB
__device__ __nv_bfloat16 g_h2 [(size_t)NS * H_];    // 64 MB
__device__ int g_cntX [MBLKS];
__device__ int g_cntW1[NT1];
__device__ int g_cntW2[NT1];
__device__ int g_cnt1 [MBLKS];
__device__ int g_cnt2 [MBLKS];

// ----------------------------------------------------------------------------
// PTX helpers
// ----------------------------------------------------------------------------
__device__ __forceinline__ void cp16(uint32_t dst, const void* src) {
    asm volatile("cp.async.cg.shared.global [%0], [%1], 16;" :: "r"(dst), "l"(src));
}
__device__ __forceinline__ void cp_commit() {
    asm volatile("cp.async.commit_group;");
}
template<int N> __device__ __forceinline__ void cp_wait() {
    asm volatile("cp.async.wait_group %0;" :: "n"(N));
}
__device__ __forceinline__ void ldsm_x4(uint32_t* r, uint32_t addr) {
    asm volatile("ldmatrix.sync.aligned.m8n8.x4.shared.b16 {%0,%1,%2,%3}, [%4];"
                 : "=r"(r[0]), "=r"(r[1]), "=r"(r[2]), "=r"(r[3]) : "r"(addr));
}
__device__ __forceinline__ void mma_fp8_h(uint32_t* d, const uint32_t* a,
                                          const uint32_t* b) {
    asm volatile("mma.sync.aligned.m16n8k32.row.col.f16.e4m3.e4m3.f16 "
                 "{%0,%1}, {%2,%3,%4,%5}, {%6,%7}, {%0,%1};"
                 : "+r"(d[0]), "+r"(d[1])
                 : "r"(a[0]), "r"(a[1]), "r"(a[2]), "r"(a[3]),
                   "r"(b[0]), "r"(b[1]));
}
__device__ __forceinline__ unsigned char f2e4m3(float v) {
    return (unsigned char)__nv_cvt_float_to_fp8(v, __NV_SATFINITE, __NV_E4M3);
}
__device__ __forceinline__ uint32_t pack4(float4 v, float s) {
    return (uint32_t)f2e4m3(v.x * s)
         | ((uint32_t)f2e4m3(v.y * s) << 8)
         | ((uint32_t)f2e4m3(v.z * s) << 16)
         | ((uint32_t)f2e4m3(v.w * s) << 24);
}

// spin until *cnt >= target (thread 0), then block-wide fence
__device__ __forceinline__ void wait_cnt(int* cnt, int target) {
    if (threadIdx.x == 0)
        while (atomicAdd(cnt, 0) < target) __nanosleep(64);
    __syncthreads();
    __threadfence();
}
// make this CTA's writes visible, then bump counter
__device__ __forceinline__ void publish(int* cnt) {
    __threadfence();
    __syncthreads();
    if (threadIdx.x == 0) atomicAdd(cnt, 1);
}
// block-reduce s and add -0.5*s/VAR to out
__device__ __forceinline__ void prior_add(float s, float* out) {
    #pragma unroll
    for (int o = 16; o; o >>= 1) s += __shfl_xor_sync(0xFFFFFFFFu, s, o);
    __shared__ float ws[8];
    if ((threadIdx.x & 31) == 0) ws[threadIdx.x >> 5] = s;
    __syncthreads();
    if (threadIdx.x < 8) {
        float t = ws[threadIdx.x];
        #pragma unroll
        for (int o = 4; o; o >>= 1) t += __shfl_xor_sync(0xFFu, t, o);
        if (threadIdx.x == 0) atomicAdd(out, (float)(-0.5 / PRIOR_VAR) * t);
    }
}

// ----------------------------------------------------------------------------
// Mega-kernel: conv + dual GEMM + loss, ordered by bid (all deps point down).
// GEMM: BK=128, 2 stages — halves per-iteration barrier/pipeline overhead.
// ----------------------------------------------------------------------------
#define BM 256
#define BN 128
#define BK 128
#define STAGES 2
#define ROWB 144
#define A_STG (BM * ROWB)              // 36864
#define B_STG (BN * ROWB)              // 18432
#define STG_BYTES (A_STG + B_STG)      // 55296
#define SMEM_DYN (STAGES * STG_BYTES)  // 110592; x2 CTAs = 221184

__global__ __launch_bounds__(256, 2)
void mega_kernel(const float* __restrict__ X,
                 const float* __restrict__ W1, const float* __restrict__ b1,
                 const float* __restrict__ W2, const float* __restrict__ b2,
                 const float* __restrict__ W3, const float* __restrict__ b3,
                 const int*   __restrict__ Y,  float* __restrict__ out)
{
    extern __shared__ unsigned char smem[];
    const int bid = blockIdx.x;
    const int tid = threadIdx.x;

    // ---------------- conversion phase (bids 0..352) ----------------
    if (bid < N_CONVX) {
        int blk = bid >> 2, q = bid & 3;
        size_t base4 = (((size_t)blk * 256 + q * 64) * INF_) >> 2;
        const float4* src = (const float4*)X + base4;
        uint32_t* dst = (uint32_t*)g_Xq + base4;
        for (int i = tid; i < 16384; i += 256)
            dst[i] = pack4(src[i], 1.0f);
        publish(&g_cntX[blk]);
        return;
    }
    if (bid < N_CONVX + N_CONVW1) {
        int b2i = bid - N_CONVX, blk = b2i >> 1, hf = b2i & 1;
        size_t base4 = (((size_t)blk * 128 + hf * 64) * INF_) >> 2;
        const float4* src = (const float4*)W1 + base4;
        uint32_t* dst = (uint32_t*)g_W1q + base4;
        float s = 0.f;
        for (int i = tid; i < 16384; i += 256) {
            float4 v = src[i];
            dst[i] = pack4(v, SCALE_W);
            s += v.x * v.x + v.y * v.y + v.z * v.z + v.w * v.w;
        }
        prior_add(s, out);
        publish(&g_cntW1[blk]);
        return;
    }
    if (bid < BID_SMALL) {
        int b2i = bid - (N_CONVX + N_CONVW1), blk = b2i >> 2, q = b2i & 3;
        size_t base4 = (((size_t)blk * 128 + q * 32) * H_) >> 2;
        const float4* src = (const float4*)W2 + base4;
        uint32_t* dst = (uint32_t*)g_W2q + base4;
        float s = 0.f;
        for (int i = tid; i < 16384; i += 256) {
            float4 v = src[i];
            dst[i] = pack4(v, SCALE_W);
            s += v.x * v.x + v.y * v.y + v.z * v.z + v.w * v.w;
        }
        prior_add(s, out);
        publish(&g_cntW2[blk]);
        return;
    }
    if (bid == BID_SMALL) {
        float s = 0.f;
        for (int i = tid; i < H_; i += 256) { float v = b1[i]; s += v * v; }
        for (int i = tid; i < H_; i += 256) { float v = b2[i]; s += v * v; }
        for (int i = tid; i < NC * H_; i += 256) { float v = W3[i]; s += v * v; }
        for (int i = tid; i < NC; i += 256) { float v = b3[i]; s += v * v; }
        prior_add(s, out);
        return;
    }

    // ---------------- loss phase (bids >= BID_LOSS) ----------------
    if (bid >= BID_LOSS) {
        int lb = bid - BID_LOSS;                 // 0..1023, 16 rows each
        __nv_bfloat16* sW = (__nv_bfloat16*)smem;  // 40 KB of dynamic smem
        __shared__ float sSum;
        if (tid == 0) sSum = 0.f;
        for (int i = tid; i < NC * H_ / 2; i += 256) {
            float2 w2 = ((const float2*)W3)[i];
            *(__nv_bfloat162*)(sW + 2 * i) = __floats2bfloat162_rn(w2.x, w2.y);
        }
        wait_cnt(&g_cnt2[lb >> 4], NT1);         // includes __syncthreads
        const int lane = tid & 31, warp = tid >> 5;
        float local = 0.f;
        #pragma unroll
        for (int rr = 0; rr < 2; rr++) {
            int row = lb * 16 + warp * 2 + rr;
            const __nv_bfloat16* hr = g_h2 + (size_t)row * H_;
            float acc[NC];
            #pragma unroll
            for (int c = 0; c < NC; c++) acc[c] = 0.f;
            #pragma unroll 4
            for (int i = 0; i < H_ / 128; i++) {
                int k = i * 128 + lane * 4;
                uint2 hp = *(const uint2*)(hr + k);
                float2 ha = __bfloat1622float2(*(const __nv_bfloat162*)&hp.x);
                float2 hb = __bfloat1622float2(*(const __nv_bfloat162*)&hp.y);
                #pragma unroll
                for (int c = 0; c < NC; c++) {
                    uint2 wp = *(const uint2*)(sW + c * H_ + k);
                    float2 wa = __bfloat1622float2(*(const __nv_bfloat162*)&wp.x);
                    float2 wb = __bfloat1622float2(*(const __nv_bfloat162*)&wp.y);
                    acc[c] += ha.x * wa.x + ha.y * wa.y + hb.x * wb.x + hb.y * wb.y;
                }
            }
            #pragma unroll
            for (int c = 0; c < NC; c++) {
                #pragma unroll
                for (int o = 16; o; o >>= 1)
                    acc[c] += __shfl_xor_sync(0xFFFFFFFFu, acc[c], o);
            }
            if (lane == 0) {
                float lg[NC];
                float m = -1e30f;
                #pragma unroll
                for (int c = 0; c < NC; c++) {
                    lg[c] = acc[c] + b3[c];
                    m = fmaxf(m, lg[c]);
                }
                float se = 0.f;
                #pragma unroll
                for (int c = 0; c < NC; c++) se += expf(lg[c] - m);
                local += lg[Y[row]] - (m + logf(se));
            }
        }
        if (lane == 0) atomicAdd(&sSum, local);
        __syncthreads();
        if (tid == 0) atomicAdd(out, sSum);
        return;
    }

    // ---------------- GEMM phase (BK=128, 2-stage) ----------------
    const int which = (bid < BID_G2) ? 0 : 1;
    const int t     = which ? (bid - BID_G2) : (bid - BID_G1);
    const int bnIdx = t & 15;
    const int bmIdx = t >> 4;
    const int bm    = bmIdx * BM;
    const int bn    = bnIdx * BN;
    const int K     = which ? H_ : INF_;
    const float* bias = which ? b2 : b1;
    const unsigned char* __restrict__ A = which ? g_h1q : g_Xq;
    const unsigned char* __restrict__ B = which ? g_W2q : g_W1q;

    if (which) {
        if (tid == 0) {
            while (atomicAdd(&g_cnt1[bmIdx], 0) < NT1) __nanosleep(64);
            while (atomicAdd(&g_cntW2[bnIdx], 0) < 4)  __nanosleep(64);
        }
        __syncthreads();
        __threadfence();
    } else {
        if (tid == 0) {
            while (atomicAdd(&g_cntX[bmIdx], 0) < 4)  __nanosleep(64);
            while (atomicAdd(&g_cntW1[bnIdx], 0) < 2) __nanosleep(64);
        }
        __syncthreads();
        __threadfence();
    }

    uint32_t sb;
    asm("{ .reg .u64 t; cvta.to.shared.u64 t, %1; cvt.u32.u64 %0, t; }"
        : "=r"(sb) : "l"(smem));

    const int lane = tid & 31;
    const int warp = tid >> 5;
    const int wm   = warp >> 1;
    const int wn   = warp & 1;

    uint32_t acc[4][8][2];
    #pragma unroll
    for (int i = 0; i < 4; i++)
        #pragma unroll
        for (int j = 0; j < 8; j++) { acc[i][j][0] = 0u; acc[i][j][1] = 0u; }

    const int KT = K / BK;

    // one stage: A 256 rows x 128B (2048 chunks) + B 128 rows x 128B (1024)
    auto load_stage = [&](int st, int kt) {
        uint32_t aB = sb + st * STG_BYTES;
        uint32_t bB = aB + A_STG;
        const unsigned char* Ap = A + (size_t)bm * K + kt * BK;
        const unsigned char* Bp = B + (size_t)bn * K + kt * BK;
        #pragma unroll
        for (int q = 0; q < 8; q++) {
            int idx = tid + q * 256;
            int r = idx >> 3, c = (idx & 7) * 16;
            cp16(aB + r * ROWB + c, Ap + (size_t)r * K + c);
        }
        #pragma unroll
        for (int q = 0; q < 4; q++) {
            int idx = tid + q * 256;
            int r = idx >> 3, c = (idx & 7) * 16;
            cp16(bB + r * ROWB + c, Bp + (size_t)r * K + c);
        }
    };

    load_stage(0, 0);
    cp_commit();

    const uint32_t aOffBase =
        (uint32_t)((wm * 64 + (lane & 15)) * ROWB + (lane >> 4) * 16);
    const uint32_t bOffBase =
        (uint32_t)((wn * 64 + ((lane >> 4) & 1) * 8 + (lane & 7)) * ROWB +
                   ((lane >> 3) & 1) * 16);

    for (int i = 0; i < KT; i++) {
        const int s = i & 1;
        cp_wait<0>();            // group for iter i (sole outstanding) done
        __syncthreads();         // all warps past iter i-1's reads of buf s^1
        if (i + 1 < KT) load_stage(s ^ 1, i + 1);
        cp_commit();

        const uint32_t aBase = sb + s * STG_BYTES;
        const uint32_t bBase = aBase + A_STG;
        #pragma unroll
        for (int ks = 0; ks < 4; ks++) {         // four k32 steps per BK=128
            uint32_t aF[4][4];
            uint32_t bF[4][4];
            #pragma unroll
            for (int mi = 0; mi < 4; mi++)
                ldsm_x4(aF[mi], aBase + ks * 32 + aOffBase + mi * 16 * ROWB);
            #pragma unroll
            for (int njp = 0; njp < 4; njp++)
                ldsm_x4(bF[njp], bBase + ks * 32 + bOffBase + njp * 16 * ROWB);
            #pragma unroll
            for (int njp = 0; njp < 4; njp++) {
                #pragma unroll
                for (int h = 0; h < 2; h++) {
                    #pragma unroll
                    for (int mi = 0; mi < 4; mi++)
                        mma_fp8_h(acc[mi][njp * 2 + h], aF[mi], &bF[njp][2 * h]);
                }
            }
        }
    }

    // epilogue
    const float inv = which ? INV_G2 : INV_G1;
    #pragma unroll
    for (int mi = 0; mi < 4; mi++) {
        int row0 = bm + wm * 64 + mi * 16 + (lane >> 2);
        #pragma unroll
        for (int nj = 0; nj < 8; nj++) {
            int col = bn + wn * 64 + nj * 8 + 2 * (lane & 3);
            float bv0 = __ldg(bias + col), bv1 = __ldg(bias + col + 1);
            float2 f01 = __half22float2(*(const __half2*)&acc[mi][nj][0]);
            float2 f23 = __half22float2(*(const __half2*)&acc[mi][nj][1]);
            float v0 = fmaxf(f01.x * inv + bv0, 0.f);
            float v1 = fmaxf(f01.y * inv + bv1, 0.f);
            float v2 = fmaxf(f23.x * inv + bv0, 0.f);
            float v3 = fmaxf(f23.y * inv + bv1, 0.f);
            if (which == 0) {
                unsigned short p0 = (unsigned short)f2e4m3(v0 * SCALE_H) |
                                    ((unsigned short)f2e4m3(v1 * SCALE_H) << 8);
                unsigned short p1 = (unsigned short)f2e4m3(v2 * SCALE_H) |
                                    ((unsigned short)f2e4m3(v3 * SCALE_H) << 8);
                *(unsigned short*)(g_h1q + (size_t)row0 * H_ + col)       = p0;
                *(unsigned short*)(g_h1q + (size_t)(row0 + 8) * H_ + col) = p1;
            } else {
                *(__nv_bfloat162*)(g_h2 + (size_t)row0 * H_ + col) =
                    __floats2bfloat162_rn(v0, v1);
                *(__nv_bfloat162*)(g_h2 + (size_t)(row0 + 8) * H_ + col) =
                    __floats2bfloat162_rn(v2, v3);
            }
        }
    }

    publish(which ? &g_cnt2[bmIdx] : &g_cnt1[bmIdx]);
}

// ----------------------------------------------------------------------------
// init: prior constant + zero ALL counters (every graph replay).
// ----------------------------------------------------------------------------
__global__ void init_kernel(float* out, float c) {
    int t = threadIdx.x;
    if (t == 0) out[0] = c;
    if (t < MBLKS) { g_cntX[t] = 0; g_cnt1[t] = 0; g_cnt2[t] = 0; }
    if (t < NT1)   { g_cntW1[t] = 0; g_cntW2[t] = 0; }
}

// ----------------------------------------------------------------------------
// kernel_launch  (2 launches)
// ----------------------------------------------------------------------------
extern "C" void kernel_launch(void* const* d_in, const int* in_sizes, int n_in,
                              void* d_out, int out_size)
{
    const float* X  = (const float*)d_in[0];
    const int*   Y  = (const int*)  d_in[1];
    const float* W1 = (const float*)d_in[2];
    const float* b1 = (const float*)d_in[3];
    const float* W2 = (const float*)d_in[4];
    const float* b2 = (const float*)d_in[5];
    const float* W3 = (const float*)d_in[6];
    const float* b3 = (const float*)d_in[7];
    float* out = (float*)d_out;

    cudaFuncSetAttribute(mega_kernel,
                         cudaFuncAttributeMaxDynamicSharedMemorySize, SMEM_DYN);

    double d = 0.0;
    for (int i = 2; i < 8; i++) d += (double)in_sizes[i];
    float cterm = (float)(-0.5 * d * log(2.0 * M_PI * PRIOR_VAR));
    init_kernel<<<1, 64>>>(out, cterm);                                 // 0

    mega_kernel<<<GRID_TOT, 256, SMEM_DYN>>>(X, W1, b1, W2, b2,
                                             W3, b3, Y, out);           // 1
}